// round 2
// baseline (speedup 1.0000x reference)
#include <cuda_runtime.h>
#include <math.h>

// Problem constants (fixed by the dataset)
#define Bc 8
#define Nc 20000
#define Hc 15
#define Kc 25
#define Gc 64
#define Ec 640000
#define Cc 6
#define Fp 128                      // padded feature dim: B*H = 120 -> 128
#define PLANE ((size_t)Nc * Fp)     // floats per plane = 2,560,000 (10 MB)
#define EGRID 888                   // einsum grid

struct __align__(8) EdgeT { int c; float w; };

// Scratch (device globals: allocation-free rule)
__device__ float g_TxAll[(size_t)Kc * PLANE];   // 256 MB: all 25 Chebyshev planes
__device__ int   g_deg[Nc];
__device__ float g_dinv[Nc];
__device__ int   g_rowptr[Nc + 1];
__device__ int   g_cursor[Nc];
__device__ EdgeT g_csr[Ec];
__device__ float g_partial[EGRID * Bc * Cc];

// ---------------------------------------------------------------------------
__global__ void k_zero() {
    int i = blockIdx.x * blockDim.x + threadIdx.x;
    if (i < Nc) { g_deg[i] = 0; g_cursor[i] = 0; }
}

__global__ void k_deg(const int* __restrict__ ei) {
    int e = blockIdx.x * blockDim.x + threadIdx.x;
    if (e < Ec) atomicAdd(&g_deg[ei[e]], 1);   // row = edge_index[0]
}

__global__ void k_dinv() {
    int i = blockIdx.x * blockDim.x + threadIdx.x;
    if (i < Nc) {
        int d = g_deg[i];
        g_dinv[i] = (d > 0) ? rsqrtf((float)d) : 0.0f;
    }
}

// Single-block exclusive scan of g_deg -> g_rowptr (1024 thr * 20 nodes/thr)
__global__ void k_scan() {
    __shared__ int ss[1024];
    const int CH = 20;
    int tid = threadIdx.x;
    int st = tid * CH;
    int s = 0;
    #pragma unroll
    for (int i = 0; i < CH; i++) {
        int idx = st + i;
        if (idx < Nc) s += g_deg[idx];
    }
    ss[tid] = s;
    __syncthreads();
    for (int off = 1; off < 1024; off <<= 1) {
        int v = (tid >= off) ? ss[tid - off] : 0;
        __syncthreads();
        ss[tid] += v;
        __syncthreads();
    }
    int run = ss[tid] - s;   // exclusive prefix of this chunk
    for (int i = 0; i < CH; i++) {
        int idx = st + i;
        if (idx < Nc) { g_rowptr[idx] = run; run += g_deg[idx]; }
    }
    if (tid == 1023) g_rowptr[Nc] = ss[1023];
}

__global__ void k_fill(const int* __restrict__ ei) {
    int e = blockIdx.x * blockDim.x + threadIdx.x;
    if (e < Ec) {
        int r = ei[e];
        int c = ei[Ec + e];
        int pos = g_rowptr[r] + atomicAdd(&g_cursor[r], 1);
        EdgeT t;
        t.c = c;
        t.w = -(g_dinv[r] * g_dinv[c]);   // norm = -(dinv[row]*dinv[col])
        g_csr[pos] = t;
    }
}

// plane 0 = x transposed to [N, b*H+h], pad features 120..127 = 0
__global__ void k_init(const float* __restrict__ x) {
    int i = blockIdx.x * blockDim.x + threadIdx.x;
    if (i < Nc * Fp) {
        int n = i >> 7, f = i & 127;
        float v = 0.0f;
        if (f < Bc * Hc) {
            int b = f / Hc, h = f - b * Hc;
            v = x[((size_t)b * Nc + n) * Hc + h];
        }
        g_TxAll[i] = v;
    }
}

// Warp-per-node CSR gather SpMM: out = (first ? L*in : 2*L*in - prev)
// Unroll-4: batch the 4 edge descriptors + 4 gathers before the FMAs (MLP).
__global__ void __launch_bounds__(512) k_prop(int kin, int kprev, int kout, int first) {
    int warp = blockIdx.x * (blockDim.x >> 5) + (threadIdx.x >> 5);
    int lane = threadIdx.x & 31;
    if (warp >= Nc || lane >= 30) return;   // 30 lanes * float4 = 120 features
    const float4* __restrict__ in4 = (const float4*)(g_TxAll + (size_t)kin * PLANE);
    float4* out4 = (float4*)(g_TxAll + (size_t)kout * PLANE);
    int s = g_rowptr[warp], e = g_rowptr[warp + 1];
    float4 a0 = make_float4(0.f, 0.f, 0.f, 0.f);
    float4 a1 = make_float4(0.f, 0.f, 0.f, 0.f);
    float4 a2 = make_float4(0.f, 0.f, 0.f, 0.f);
    float4 a3 = make_float4(0.f, 0.f, 0.f, 0.f);
    int j = s;
    for (; j + 4 <= e; j += 4) {
        EdgeT e0 = g_csr[j];
        EdgeT e1 = g_csr[j + 1];
        EdgeT e2 = g_csr[j + 2];
        EdgeT e3 = g_csr[j + 3];
        float4 v0 = __ldg(&in4[(size_t)e0.c * 32 + lane]);
        float4 v1 = __ldg(&in4[(size_t)e1.c * 32 + lane]);
        float4 v2 = __ldg(&in4[(size_t)e2.c * 32 + lane]);
        float4 v3 = __ldg(&in4[(size_t)e3.c * 32 + lane]);
        a0.x = fmaf(e0.w, v0.x, a0.x); a0.y = fmaf(e0.w, v0.y, a0.y);
        a0.z = fmaf(e0.w, v0.z, a0.z); a0.w = fmaf(e0.w, v0.w, a0.w);
        a1.x = fmaf(e1.w, v1.x, a1.x); a1.y = fmaf(e1.w, v1.y, a1.y);
        a1.z = fmaf(e1.w, v1.z, a1.z); a1.w = fmaf(e1.w, v1.w, a1.w);
        a2.x = fmaf(e2.w, v2.x, a2.x); a2.y = fmaf(e2.w, v2.y, a2.y);
        a2.z = fmaf(e2.w, v2.z, a2.z); a2.w = fmaf(e2.w, v2.w, a2.w);
        a3.x = fmaf(e3.w, v3.x, a3.x); a3.y = fmaf(e3.w, v3.y, a3.y);
        a3.z = fmaf(e3.w, v3.z, a3.z); a3.w = fmaf(e3.w, v3.w, a3.w);
    }
    for (; j < e; j++) {
        EdgeT e0 = g_csr[j];
        float4 v0 = __ldg(&in4[(size_t)e0.c * 32 + lane]);
        a0.x = fmaf(e0.w, v0.x, a0.x); a0.y = fmaf(e0.w, v0.y, a0.y);
        a0.z = fmaf(e0.w, v0.z, a0.z); a0.w = fmaf(e0.w, v0.w, a0.w);
    }
    float4 acc;
    acc.x = (a0.x + a1.x) + (a2.x + a3.x);
    acc.y = (a0.y + a1.y) + (a2.y + a3.y);
    acc.z = (a0.z + a1.z) + (a2.z + a3.z);
    acc.w = (a0.w + a1.w) + (a2.w + a3.w);
    float4 r;
    if (first) {
        r = acc;
    } else {
        const float4* pv = (const float4*)(g_TxAll + (size_t)kprev * PLANE);
        float4 p = pv[(size_t)warp * 32 + lane];
        r.x = fmaf(2.f, acc.x, -p.x); r.y = fmaf(2.f, acc.y, -p.y);
        r.z = fmaf(2.f, acc.z, -p.z); r.w = fmaf(2.f, acc.w, -p.w);
    }
    out4[(size_t)warp * 32 + lane] = r;
}

// Fused: h[n,b,g] = relu(sum_k Tx_k[n,b,:] @ W[k] + bias); per-block logit
// partials in registers. warp = b, lane handles g = {2l, 2l+1}.
__global__ void __launch_bounds__(256) k_einsum(const float* __restrict__ W,
                                               const float* __restrict__ bias,
                                               const float* __restrict__ fc_w) {
    __shared__ float txsh[Kc * Fp];   // 12.8 KB
    int tid = threadIdx.x;
    int b = tid >> 5, lane = tid & 31;
    float p[Cc];
    #pragma unroll
    for (int c = 0; c < Cc; c++) p[c] = 0.f;
    float bi0 = __ldg(&bias[2 * lane]);
    float bi1 = __ldg(&bias[2 * lane + 1]);
    const float4* planes = (const float4*)g_TxAll;

    for (int n = blockIdx.x; n < Nc; n += gridDim.x) {
        float4* t4 = (float4*)txsh;
        #pragma unroll 4
        for (int i = tid; i < Kc * 32; i += 256) {
            int k = i >> 5, q = i & 31;
            t4[i] = planes[(size_t)k * (PLANE / 4) + (size_t)n * 32 + q];
        }
        __syncthreads();
        float a0 = 0.f, a1 = 0.f;
        for (int k = 0; k < Kc; k++) {
            const float* tb = txsh + k * Fp + b * Hc;
            const float2* wr = (const float2*)(W + (size_t)k * Hc * Gc);
            #pragma unroll
            for (int h = 0; h < Hc; h++) {
                float t = tb[h];                       // LDS broadcast
                float2 wv = __ldg(&wr[h * 32 + lane]); // L1-resident (96 KB)
                a0 = fmaf(t, wv.x, a0);
                a1 = fmaf(t, wv.y, a1);
            }
        }
        float h0 = fmaxf(a0 + bi0, 0.f);
        float h1 = fmaxf(a1 + bi1, 0.f);
        const float* fw = fc_w + (size_t)n * Gc + 2 * lane;
        #pragma unroll
        for (int c = 0; c < Cc; c++) {
            float2 wv = __ldg((const float2*)(fw + (size_t)c * Nc * Gc));
            p[c] = fmaf(h0, wv.x, fmaf(h1, wv.y, p[c]));
        }
        __syncthreads();
    }
    #pragma unroll
    for (int c = 0; c < Cc; c++) {
        #pragma unroll
        for (int off = 16; off > 0; off >>= 1)
            p[c] += __shfl_down_sync(0xffffffffu, p[c], off);
    }
    if (lane == 0) {
        #pragma unroll
        for (int c = 0; c < Cc; c++)
            g_partial[((size_t)blockIdx.x * Bc + b) * Cc + c] = p[c];
    }
}

// Deterministic reduction of partials + fc_b + log_softmax -> d_out [8,6]
__global__ void k_final(const float* __restrict__ fc_b, float* __restrict__ out) {
    __shared__ float lg[Bc * Cc];
    int tid = threadIdx.x;
    if (tid < Bc * Cc) {
        float s = 0.f;
        for (int j = 0; j < EGRID; j++) s += g_partial[j * (Bc * Cc) + tid];
        lg[tid] = s + fc_b[tid % Cc];
    }
    __syncthreads();
    if (tid < Bc) {
        float m = -1e30f;
        #pragma unroll
        for (int c = 0; c < Cc; c++) m = fmaxf(m, lg[tid * Cc + c]);
        float se = 0.f;
        #pragma unroll
        for (int c = 0; c < Cc; c++) se += expf(lg[tid * Cc + c] - m);
        float lse = m + logf(se);
        #pragma unroll
        for (int c = 0; c < Cc; c++) out[tid * Cc + c] = lg[tid * Cc + c] - lse;
    }
}

// ---------------------------------------------------------------------------
extern "C" void kernel_launch(void* const* d_in, const int* in_sizes, int n_in,
                              void* d_out, int out_size) {
    const float* x    = (const float*)d_in[0];   // [B,N,H]
    const int*   ei   = (const int*)d_in[1];     // [2,E]
    const float* W    = (const float*)d_in[2];   // [K,H,G]
    const float* bias = (const float*)d_in[3];   // [G]
    const float* fc_w = (const float*)d_in[4];   // [C, N*G]
    const float* fc_b = (const float*)d_in[5];   // [C]
    float* out = (float*)d_out;                  // [B,C]

    k_zero<<<(Nc + 255) / 256, 256>>>();
    k_deg<<<(Ec + 255) / 256, 256>>>(ei);
    k_dinv<<<(Nc + 255) / 256, 256>>>();
    k_scan<<<1, 1024>>>();
    k_fill<<<(Ec + 255) / 256, 256>>>(ei);
    k_init<<<(Nc * Fp + 255) / 256, 256>>>(x);

    // Chebyshev recursion: plane1 = L*plane0; plane_k = 2*L*plane_{k-1} - plane_{k-2}
    const int PBLK = 512;                 // 16 warps/block, warp-per-node
    const int PGRID = (Nc * 32 + PBLK - 1) / PBLK;
    k_prop<<<PGRID, PBLK>>>(0, 0, 1, 1);
    for (int k = 2; k < Kc; k++)
        k_prop<<<PGRID, PBLK>>>(k - 1, k - 2, k, 0);

    k_einsum<<<EGRID, 256>>>(W, bias, fc_w);
    k_final<<<1, 64>>>(fc_b, out);
}

// round 3
// speedup vs baseline: 1.1583x; 1.1583x over previous
#include <cuda_runtime.h>
#include <math.h>

// Problem constants (fixed by the dataset)
#define Bc 8
#define Nc 20000
#define Hc 15
#define Kc 25
#define Gc 64
#define Ec 640000
#define Cc 6
#define Fp 128                      // padded feature dim: B*H = 120 -> 128
#define PLANE ((size_t)Nc * Fp)     // floats per plane = 2,560,000 (10 MB)
#define EGRID 1000                  // einsum grid (2 nodes per block-iter)

struct __align__(8) EdgeT { int c; float w; };

// Scratch (device globals: allocation-free rule)
__device__ float g_TxAll[(size_t)Kc * PLANE];   // 256 MB: all 25 Chebyshev planes
__device__ int   g_deg[Nc];
__device__ float g_dinv[Nc];
__device__ int   g_rowptr[Nc + 1];
__device__ int   g_cursor[Nc];
__device__ EdgeT g_csr[Ec];
__device__ float g_partial[EGRID * Bc * Cc];

// ---------------------------------------------------------------------------
__global__ void k_zero() {
    int i = blockIdx.x * blockDim.x + threadIdx.x;
    if (i < Nc) { g_deg[i] = 0; g_cursor[i] = 0; }
}

__global__ void k_deg(const int* __restrict__ ei) {
    int e = blockIdx.x * blockDim.x + threadIdx.x;
    if (e < Ec) atomicAdd(&g_deg[ei[e]], 1);   // row = edge_index[0]
}

// Merged: dinv computation + single-block exclusive scan of g_deg -> g_rowptr
__global__ void k_scan_dinv() {
    __shared__ int ss[1024];
    const int CH = 20;
    int tid = threadIdx.x;
    int st = tid * CH;
    int s = 0;
    #pragma unroll
    for (int i = 0; i < CH; i++) {
        int idx = st + i;
        if (idx < Nc) {
            int d = g_deg[idx];
            g_dinv[idx] = (d > 0) ? rsqrtf((float)d) : 0.0f;
            s += d;
        }
    }
    ss[tid] = s;
    __syncthreads();
    for (int off = 1; off < 1024; off <<= 1) {
        int v = (tid >= off) ? ss[tid - off] : 0;
        __syncthreads();
        ss[tid] += v;
        __syncthreads();
    }
    int run = ss[tid] - s;   // exclusive prefix of this chunk
    for (int i = 0; i < CH; i++) {
        int idx = st + i;
        if (idx < Nc) { g_rowptr[idx] = run; run += g_deg[idx]; }
    }
    if (tid == 1023) g_rowptr[Nc] = ss[1023];
}

__global__ void k_fill(const int* __restrict__ ei) {
    int e = blockIdx.x * blockDim.x + threadIdx.x;
    if (e < Ec) {
        int r = ei[e];
        int c = ei[Ec + e];
        int pos = g_rowptr[r] + atomicAdd(&g_cursor[r], 1);
        EdgeT t;
        t.c = c;
        t.w = -(g_dinv[r] * g_dinv[c]);   // norm = -(dinv[row]*dinv[col])
        g_csr[pos] = t;
    }
}

// plane 0 = x transposed to [N, b*H+h], pad features 120..127 = 0
__global__ void k_init(const float* __restrict__ x) {
    int i = blockIdx.x * blockDim.x + threadIdx.x;
    if (i < Nc * Fp) {
        int n = i >> 7, f = i & 127;
        float v = 0.0f;
        if (f < Bc * Hc) {
            int b = f / Hc, h = f - b * Hc;
            v = x[((size_t)b * Nc + n) * Hc + h];
        }
        g_TxAll[i] = v;
    }
}

// Warp-per-node CSR gather SpMM: out = (first ? L*in : 2*L*in - prev)
// Unroll-8: batch 8 edge descriptors then 8 gathers before FMAs (MLP=8/lane).
__global__ void __launch_bounds__(256) k_prop(int kin, int kprev, int kout, int first) {
    int warp = blockIdx.x * (blockDim.x >> 5) + (threadIdx.x >> 5);
    int lane = threadIdx.x & 31;
    if (warp >= Nc || lane >= 30) return;   // 30 lanes * float4 = 120 features
    const float4* __restrict__ in4 = (const float4*)(g_TxAll + (size_t)kin * PLANE);
    float4* out4 = (float4*)(g_TxAll + (size_t)kout * PLANE);
    int s = g_rowptr[warp], e = g_rowptr[warp + 1];
    float4 acc[4];
    #pragma unroll
    for (int q = 0; q < 4; q++) acc[q] = make_float4(0.f, 0.f, 0.f, 0.f);
    int j = s;
    for (; j + 8 <= e; j += 8) {
        EdgeT E[8];
        #pragma unroll
        for (int u = 0; u < 8; u++) E[u] = g_csr[j + u];
        float4 V[8];
        #pragma unroll
        for (int u = 0; u < 8; u++)
            V[u] = __ldg(&in4[(size_t)E[u].c * 32 + lane]);
        #pragma unroll
        for (int u = 0; u < 8; u++) {
            float w = E[u].w; float4 v = V[u]; int q = u & 3;
            acc[q].x = fmaf(w, v.x, acc[q].x);
            acc[q].y = fmaf(w, v.y, acc[q].y);
            acc[q].z = fmaf(w, v.z, acc[q].z);
            acc[q].w = fmaf(w, v.w, acc[q].w);
        }
    }
    for (; j + 4 <= e; j += 4) {
        EdgeT E[4];
        #pragma unroll
        for (int u = 0; u < 4; u++) E[u] = g_csr[j + u];
        float4 V[4];
        #pragma unroll
        for (int u = 0; u < 4; u++)
            V[u] = __ldg(&in4[(size_t)E[u].c * 32 + lane]);
        #pragma unroll
        for (int u = 0; u < 4; u++) {
            float w = E[u].w; float4 v = V[u];
            acc[u].x = fmaf(w, v.x, acc[u].x);
            acc[u].y = fmaf(w, v.y, acc[u].y);
            acc[u].z = fmaf(w, v.z, acc[u].z);
            acc[u].w = fmaf(w, v.w, acc[u].w);
        }
    }
    for (; j < e; j++) {
        EdgeT E0 = g_csr[j];
        float4 v = __ldg(&in4[(size_t)E0.c * 32 + lane]);
        acc[0].x = fmaf(E0.w, v.x, acc[0].x);
        acc[0].y = fmaf(E0.w, v.y, acc[0].y);
        acc[0].z = fmaf(E0.w, v.z, acc[0].z);
        acc[0].w = fmaf(E0.w, v.w, acc[0].w);
    }
    float4 a;
    a.x = (acc[0].x + acc[1].x) + (acc[2].x + acc[3].x);
    a.y = (acc[0].y + acc[1].y) + (acc[2].y + acc[3].y);
    a.z = (acc[0].z + acc[1].z) + (acc[2].z + acc[3].z);
    a.w = (acc[0].w + acc[1].w) + (acc[2].w + acc[3].w);
    float4 r;
    if (first) {
        r = a;
    } else {
        const float4* pv = (const float4*)(g_TxAll + (size_t)kprev * PLANE);
        float4 p = pv[(size_t)warp * 32 + lane];
        r.x = fmaf(2.f, a.x, -p.x); r.y = fmaf(2.f, a.y, -p.y);
        r.z = fmaf(2.f, a.z, -p.z); r.w = fmaf(2.f, a.w, -p.w);
    }
    out4[(size_t)warp * 32 + lane] = r;
}

// Fused: h[n,b,g] = relu(sum_k Tx_k[n,b,:] @ W[k] + bias); per-block logit
// partials in registers. warp = b, lane handles g = {2l, 2l+1}.
// 2-node register blocking: W loads amortized over two nodes.
__global__ void __launch_bounds__(256) k_einsum(const float* __restrict__ W,
                                               const float* __restrict__ bias,
                                               const float* __restrict__ fc_w) {
    __shared__ float txsh[2 * Kc * Fp];   // 25.6 KB: 2 node-rows x 25 planes
    int tid = threadIdx.x;
    int b = tid >> 5, lane = tid & 31;
    float p[Cc];
    #pragma unroll
    for (int c = 0; c < Cc; c++) p[c] = 0.f;
    float bi0 = __ldg(&bias[2 * lane]);
    float bi1 = __ldg(&bias[2 * lane + 1]);
    const float4* planes = (const float4*)g_TxAll;

    for (int n0 = blockIdx.x * 2; n0 < Nc; n0 += gridDim.x * 2) {
        float4* t4 = (float4*)txsh;
        #pragma unroll 4
        for (int i = tid; i < Kc * 64; i += 256) {
            int k = i >> 6, q = i & 63;            // q<32 -> node0, else node1
            int node = n0 + (q >> 5), qq = q & 31;
            t4[i] = planes[(size_t)k * (PLANE / 4) + (size_t)node * 32 + qq];
        }
        __syncthreads();
        float a00 = 0.f, a01 = 0.f, a10 = 0.f, a11 = 0.f;
        for (int k = 0; k < Kc; k++) {
            const float* tb0 = txsh + k * (2 * Fp) + b * Hc;        // node0
            const float* tb1 = tb0 + Fp;                            // node1
            const float2* wr = (const float2*)(W + (size_t)k * Hc * Gc);
            #pragma unroll
            for (int h = 0; h < Hc; h++) {
                float t0 = tb0[h];
                float t1 = tb1[h];
                float2 wv = __ldg(&wr[h * 32 + lane]);  // L1-resident (96 KB)
                a00 = fmaf(t0, wv.x, a00);
                a01 = fmaf(t0, wv.y, a01);
                a10 = fmaf(t1, wv.x, a10);
                a11 = fmaf(t1, wv.y, a11);
            }
        }
        float h00 = fmaxf(a00 + bi0, 0.f);
        float h01 = fmaxf(a01 + bi1, 0.f);
        float h10 = fmaxf(a10 + bi0, 0.f);
        float h11 = fmaxf(a11 + bi1, 0.f);
        const float* fw0 = fc_w + (size_t)n0 * Gc + 2 * lane;
        const float* fw1 = fw0 + Gc;
        #pragma unroll
        for (int c = 0; c < Cc; c++) {
            float2 w0 = __ldg((const float2*)(fw0 + (size_t)c * Nc * Gc));
            float2 w1 = __ldg((const float2*)(fw1 + (size_t)c * Nc * Gc));
            p[c] = fmaf(h00, w0.x, fmaf(h01, w0.y, p[c]));
            p[c] = fmaf(h10, w1.x, fmaf(h11, w1.y, p[c]));
        }
        __syncthreads();
    }
    #pragma unroll
    for (int c = 0; c < Cc; c++) {
        #pragma unroll
        for (int off = 16; off > 0; off >>= 1)
            p[c] += __shfl_down_sync(0xffffffffu, p[c], off);
    }
    if (lane == 0) {
        #pragma unroll
        for (int c = 0; c < Cc; c++)
            g_partial[((size_t)blockIdx.x * Bc + b) * Cc + c] = p[c];
    }
}

// Deterministic reduction of partials + fc_b + log_softmax -> d_out [8,6]
__global__ void k_final(const float* __restrict__ fc_b, float* __restrict__ out) {
    __shared__ float lg[Bc * Cc];
    int tid = threadIdx.x;
    if (tid < Bc * Cc) {
        float s = 0.f;
        for (int j = 0; j < EGRID; j++) s += g_partial[j * (Bc * Cc) + tid];
        lg[tid] = s + fc_b[tid % Cc];
    }
    __syncthreads();
    if (tid < Bc) {
        float m = -1e30f;
        #pragma unroll
        for (int c = 0; c < Cc; c++) m = fmaxf(m, lg[tid * Cc + c]);
        float se = 0.f;
        #pragma unroll
        for (int c = 0; c < Cc; c++) se += expf(lg[tid * Cc + c] - m);
        float lse = m + logf(se);
        #pragma unroll
        for (int c = 0; c < Cc; c++) out[tid * Cc + c] = lg[tid * Cc + c] - lse;
    }
}

// ---------------------------------------------------------------------------
extern "C" void kernel_launch(void* const* d_in, const int* in_sizes, int n_in,
                              void* d_out, int out_size) {
    const float* x    = (const float*)d_in[0];   // [B,N,H]
    const int*   ei   = (const int*)d_in[1];     // [2,E]
    const float* W    = (const float*)d_in[2];   // [K,H,G]
    const float* bias = (const float*)d_in[3];   // [G]
    const float* fc_w = (const float*)d_in[4];   // [C, N*G]
    const float* fc_b = (const float*)d_in[5];   // [C]
    float* out = (float*)d_out;                  // [B,C]

    k_zero<<<(Nc + 255) / 256, 256>>>();
    k_deg<<<(Ec + 255) / 256, 256>>>(ei);
    k_scan_dinv<<<1, 1024>>>();
    k_fill<<<(Ec + 255) / 256, 256>>>(ei);
    k_init<<<(Nc * Fp + 255) / 256, 256>>>(x);

    // Chebyshev recursion: plane1 = L*plane0; plane_k = 2*L*plane_{k-1} - plane_{k-2}
    const int PBLK = 256;                 // 8 warps/block, warp-per-node
    const int PGRID = (Nc + 7) / 8;
    k_prop<<<PGRID, PBLK>>>(0, 0, 1, 1);
    for (int k = 2; k < Kc; k++)
        k_prop<<<PGRID, PBLK>>>(k - 1, k - 2, k, 0);

    k_einsum<<<EGRID, 256>>>(W, bias, fc_w);
    k_final<<<1, 64>>>(fc_b, out);
}

// round 5
// speedup vs baseline: 1.4574x; 1.2582x over previous
#include <cuda_runtime.h>
#include <math.h>

// Problem constants (fixed by the dataset)
#define Bc 8
#define Nc 20000
#define Hc 15
#define Kc 25
#define Gc 64
#define Ec 640000
#define Cc 6
#define Fp 128                      // padded feature dim in GMEM planes
#define Fs 120                      // unpadded feature dim in SMEM (B*H)
#define PLANE ((size_t)Nc * Fp)     // floats per plane = 2,560,000 (10 MB)
#define EGRID 592                   // einsum grid (4 blocks/SM, 4 nodes/iter)

struct __align__(8) EdgeT { int c; float w; };

// Scratch (device globals: allocation-free rule).
// INVARIANT: g_deg and g_cursor are all-zero at kernel_launch entry.
// Established by static zero-init, re-established each call by k_scan_dinv.
__device__ float g_TxAll[(size_t)Kc * PLANE];   // 256 MB: all 25 Chebyshev planes
__device__ int   g_deg[Nc];
__device__ float g_dinv[Nc];
__device__ int   g_rowptr[Nc + 1];
__device__ int   g_cursor[Nc];
__device__ EdgeT g_csr[Ec];
__device__ float g_partial[EGRID * Bc * Cc];

// ---------------------------------------------------------------------------
__global__ void k_deg(const int* __restrict__ ei) {
    int e = blockIdx.x * blockDim.x + threadIdx.x;
    if (e < Ec) atomicAdd(&g_deg[ei[e]], 1);   // row = edge_index[0]
}

// dinv + single-block exclusive scan of g_deg -> g_rowptr.
// Also re-zeroes g_deg and g_cursor (restores the entry invariant; cursor is
// consumed by k_fill_init later in THIS launch sequence).
__global__ void k_scan_dinv() {
    __shared__ int ss[1024];
    const int CH = 20;
    int tid = threadIdx.x;
    int st = tid * CH;
    int s = 0;
    #pragma unroll
    for (int i = 0; i < CH; i++) {
        int idx = st + i;
        if (idx < Nc) {
            int d = g_deg[idx];
            g_dinv[idx] = (d > 0) ? rsqrtf((float)d) : 0.0f;
            s += d;
        }
    }
    ss[tid] = s;
    __syncthreads();
    for (int off = 1; off < 1024; off <<= 1) {
        int v = (tid >= off) ? ss[tid - off] : 0;
        __syncthreads();
        ss[tid] += v;
        __syncthreads();
    }
    int run = ss[tid] - s;   // exclusive prefix of this chunk
    for (int i = 0; i < CH; i++) {
        int idx = st + i;
        if (idx < Nc) {
            int d = g_deg[idx];
            g_rowptr[idx] = run;
            run += d;
            g_deg[idx] = 0;      // restore invariant for next launch
            g_cursor[idx] = 0;   // zero for k_fill_init below
        }
    }
    if (tid == 1023) g_rowptr[Nc] = ss[1023];
}

// Merged: CSR fill (i < Ec) + plane-0 init (i < Nc*Fp). Independent work.
__global__ void k_fill_init(const int* __restrict__ ei, const float* __restrict__ x) {
    int i = blockIdx.x * blockDim.x + threadIdx.x;
    if (i < Ec) {
        int r = ei[i];
        int c = ei[Ec + i];
        int pos = g_rowptr[r] + atomicAdd(&g_cursor[r], 1);
        EdgeT t;
        t.c = c;
        t.w = -(g_dinv[r] * g_dinv[c]);   // norm = -(dinv[row]*dinv[col])
        g_csr[pos] = t;
    }
    if (i < Nc * Fp) {
        int n = i >> 7, f = i & 127;
        float v = 0.0f;
        if (f < Bc * Hc) {
            int b = f / Hc, h = f - b * Hc;
            v = x[((size_t)b * Nc + n) * Hc + h];
        }
        g_TxAll[i] = v;
    }
}

// Warp-per-node CSR gather SpMM: out = (first ? L*in : 2*L*in - prev)
// Unroll-8: batch 8 edge descriptors then 8 gathers before FMAs (MLP=8/lane).
__global__ void __launch_bounds__(256) k_prop(int kin, int kprev, int kout, int first) {
    int warp = blockIdx.x * (blockDim.x >> 5) + (threadIdx.x >> 5);
    int lane = threadIdx.x & 31;
    if (warp >= Nc || lane >= 30) return;   // 30 lanes * float4 = 120 features
    const float4* __restrict__ in4 = (const float4*)(g_TxAll + (size_t)kin * PLANE);
    float4* out4 = (float4*)(g_TxAll + (size_t)kout * PLANE);
    int s = g_rowptr[warp], e = g_rowptr[warp + 1];
    float4 acc[4];
    #pragma unroll
    for (int q = 0; q < 4; q++) acc[q] = make_float4(0.f, 0.f, 0.f, 0.f);
    int j = s;
    for (; j + 8 <= e; j += 8) {
        EdgeT E[8];
        #pragma unroll
        for (int u = 0; u < 8; u++) E[u] = g_csr[j + u];
        float4 V[8];
        #pragma unroll
        for (int u = 0; u < 8; u++)
            V[u] = __ldg(&in4[(size_t)E[u].c * 32 + lane]);
        #pragma unroll
        for (int u = 0; u < 8; u++) {
            float w = E[u].w; float4 v = V[u]; int q = u & 3;
            acc[q].x = fmaf(w, v.x, acc[q].x);
            acc[q].y = fmaf(w, v.y, acc[q].y);
            acc[q].z = fmaf(w, v.z, acc[q].z);
            acc[q].w = fmaf(w, v.w, acc[q].w);
        }
    }
    for (; j + 4 <= e; j += 4) {
        EdgeT E[4];
        #pragma unroll
        for (int u = 0; u < 4; u++) E[u] = g_csr[j + u];
        float4 V[4];
        #pragma unroll
        for (int u = 0; u < 4; u++)
            V[u] = __ldg(&in4[(size_t)E[u].c * 32 + lane]);
        #pragma unroll
        for (int u = 0; u < 4; u++) {
            float w = E[u].w; float4 v = V[u];
            acc[u].x = fmaf(w, v.x, acc[u].x);
            acc[u].y = fmaf(w, v.y, acc[u].y);
            acc[u].z = fmaf(w, v.z, acc[u].z);
            acc[u].w = fmaf(w, v.w, acc[u].w);
        }
    }
    for (; j < e; j++) {
        EdgeT E0 = g_csr[j];
        float4 v = __ldg(&in4[(size_t)E0.c * 32 + lane]);
        acc[0].x = fmaf(E0.w, v.x, acc[0].x);
        acc[0].y = fmaf(E0.w, v.y, acc[0].y);
        acc[0].z = fmaf(E0.w, v.z, acc[0].z);
        acc[0].w = fmaf(E0.w, v.w, acc[0].w);
    }
    float4 a;
    a.x = (acc[0].x + acc[1].x) + (acc[2].x + acc[3].x);
    a.y = (acc[0].y + acc[1].y) + (acc[2].y + acc[3].y);
    a.z = (acc[0].z + acc[1].z) + (acc[2].z + acc[3].z);
    a.w = (acc[0].w + acc[1].w) + (acc[2].w + acc[3].w);
    float4 r;
    if (first) {
        r = a;
    } else {
        const float4* pv = (const float4*)(g_TxAll + (size_t)kprev * PLANE);
        float4 p = pv[(size_t)warp * 32 + lane];
        r.x = fmaf(2.f, a.x, -p.x); r.y = fmaf(2.f, a.y, -p.y);
        r.z = fmaf(2.f, a.z, -p.z); r.w = fmaf(2.f, a.w, -p.w);
    }
    out4[(size_t)warp * 32 + lane] = r;
}

// Fused: h[n,b,g] = relu(sum_k Tx_k[n,b,:] @ W[k] + bias); per-block logit
// partials in registers. warp = b, lane handles g = {2l, 2l+1}.
// 4-node register blocking; SMEM rows stored UNPADDED (stride Fs=120 floats,
// 30 quads) so 4*25*120*4 = 48000 B fits the 48 KB static-smem limit.
__global__ void __launch_bounds__(256) k_einsum(const float* __restrict__ W,
                                               const float* __restrict__ bias,
                                               const float* __restrict__ fc_w) {
    __shared__ float txsh[4 * Kc * Fs];   // 48.0 KB: 4 node-rows x 25 planes
    int tid = threadIdx.x;
    int b = tid >> 5, lane = tid & 31;
    float p[Cc];
    #pragma unroll
    for (int c = 0; c < Cc; c++) p[c] = 0.f;
    float bi0 = __ldg(&bias[2 * lane]);
    float bi1 = __ldg(&bias[2 * lane + 1]);
    const float4* planes = (const float4*)g_TxAll;

    for (int n0 = blockIdx.x * 4; n0 < Nc; n0 += gridDim.x * 4) {
        // Stage 25 planes x 4 nodes x 30 quads (pad quads skipped).
        float4* t4 = (float4*)txsh;
        for (int i = tid; i < Kc * 4 * 30; i += 256) {
            int k = i / 120;
            int rem = i - k * 120;
            int node = rem / 30, qq = rem - node * 30;
            t4[i] = planes[(size_t)k * (PLANE / 4) + (size_t)(n0 + node) * 32 + qq];
        }
        __syncthreads();
        float a[4][2];
        #pragma unroll
        for (int u = 0; u < 4; u++) { a[u][0] = 0.f; a[u][1] = 0.f; }
        for (int k = 0; k < Kc; k++) {
            const float* tb = txsh + k * (4 * Fs) + b * Hc;
            const float2* wr = (const float2*)(W + (size_t)k * Hc * Gc);
            #pragma unroll
            for (int h = 0; h < Hc; h++) {
                float t0 = tb[h];
                float t1 = tb[Fs + h];
                float t2 = tb[2 * Fs + h];
                float t3 = tb[3 * Fs + h];
                float2 wv = __ldg(&wr[h * 32 + lane]);  // L1-resident (96 KB)
                a[0][0] = fmaf(t0, wv.x, a[0][0]); a[0][1] = fmaf(t0, wv.y, a[0][1]);
                a[1][0] = fmaf(t1, wv.x, a[1][0]); a[1][1] = fmaf(t1, wv.y, a[1][1]);
                a[2][0] = fmaf(t2, wv.x, a[2][0]); a[2][1] = fmaf(t2, wv.y, a[2][1]);
                a[3][0] = fmaf(t3, wv.x, a[3][0]); a[3][1] = fmaf(t3, wv.y, a[3][1]);
            }
        }
        float hh[4][2];
        #pragma unroll
        for (int u = 0; u < 4; u++) {
            hh[u][0] = fmaxf(a[u][0] + bi0, 0.f);
            hh[u][1] = fmaxf(a[u][1] + bi1, 0.f);
        }
        const float* fw = fc_w + (size_t)n0 * Gc + 2 * lane;
        #pragma unroll
        for (int c = 0; c < Cc; c++) {
            const float* fwc = fw + (size_t)c * Nc * Gc;
            #pragma unroll
            for (int u = 0; u < 4; u++) {
                float2 wv = __ldg((const float2*)(fwc + u * Gc));
                p[c] = fmaf(hh[u][0], wv.x, fmaf(hh[u][1], wv.y, p[c]));
            }
        }
        __syncthreads();
    }
    #pragma unroll
    for (int c = 0; c < Cc; c++) {
        #pragma unroll
        for (int off = 16; off > 0; off >>= 1)
            p[c] += __shfl_down_sync(0xffffffffu, p[c], off);
    }
    if (lane == 0) {
        #pragma unroll
        for (int c = 0; c < Cc; c++)
            g_partial[((size_t)blockIdx.x * Bc + b) * Cc + c] = p[c];
    }
}

// Deterministic reduction of partials + fc_b + log_softmax -> d_out [8,6]
__global__ void k_final(const float* __restrict__ fc_b, float* __restrict__ out) {
    __shared__ float lg[Bc * Cc];
    int tid = threadIdx.x;
    if (tid < Bc * Cc) {
        float s = 0.f;
        for (int j = 0; j < EGRID; j++) s += g_partial[j * (Bc * Cc) + tid];
        lg[tid] = s + fc_b[tid % Cc];
    }
    __syncthreads();
    if (tid < Bc) {
        float m = -1e30f;
        #pragma unroll
        for (int c = 0; c < Cc; c++) m = fmaxf(m, lg[tid * Cc + c]);
        float se = 0.f;
        #pragma unroll
        for (int c = 0; c < Cc; c++) se += expf(lg[tid * Cc + c] - m);
        float lse = m + logf(se);
        #pragma unroll
        for (int c = 0; c < Cc; c++) out[tid * Cc + c] = lg[tid * Cc + c] - lse;
    }
}

// ---------------------------------------------------------------------------
extern "C" void kernel_launch(void* const* d_in, const int* in_sizes, int n_in,
                              void* d_out, int out_size) {
    const float* x    = (const float*)d_in[0];   // [B,N,H]
    const int*   ei   = (const int*)d_in[1];     // [2,E]
    const float* W    = (const float*)d_in[2];   // [K,H,G]
    const float* bias = (const float*)d_in[3];   // [G]
    const float* fc_w = (const float*)d_in[4];   // [C, N*G]
    const float* fc_b = (const float*)d_in[5];   // [C]
    float* out = (float*)d_out;                  // [B,C]

    k_deg<<<(Ec + 255) / 256, 256>>>(ei);                       // idx 0
    k_scan_dinv<<<1, 1024>>>();                                 // idx 1
    k_fill_init<<<(Nc * Fp + 255) / 256, 256>>>(ei, x);         // idx 2

    // Chebyshev recursion: plane1 = L*plane0; plane_k = 2*L*plane_{k-1} - plane_{k-2}
    const int PBLK = 256;                 // 8 warps/block, warp-per-node
    const int PGRID = (Nc + 7) / 8;
    k_prop<<<PGRID, PBLK>>>(0, 0, 1, 1);                        // idx 3 <- ncu capture
    for (int k = 2; k < Kc; k++)
        k_prop<<<PGRID, PBLK>>>(k - 1, k - 2, k, 0);

    k_einsum<<<EGRID, 256>>>(W, bias, fc_w);
    k_final<<<1, 64>>>(fc_b, out);
}

// round 6
// speedup vs baseline: 1.5364x; 1.0542x over previous
#include <cuda_runtime.h>
#include <cuda_fp16.h>
#include <math.h>

// Problem constants (fixed by the dataset)
#define Bc 8
#define Nc 20000
#define Hc 15
#define Kc 25
#define Gc 64
#define Ec 640000
#define Cc 6
#define Fp 128                      // padded feature dim in GMEM planes
#define Fs 120                      // unpadded feature dim in SMEM (B*H)
#define PLANE ((size_t)Nc * Fp)     // floats per plane = 2,560,000 (10 MB)
#define EGRID 592                   // einsum grid (4 blocks/SM, 4 nodes/iter)

struct __align__(8) EdgeT { int c; float w; };

// Scratch (device globals: allocation-free rule).
// INVARIANT: g_deg and g_cursor are all-zero at kernel_launch entry.
__device__ float  g_TxAll[(size_t)Kc * PLANE];   // 256 MB: fp32 recursion planes
__device__ __half g_TxH[2][(size_t)Nc * Fp];     // fp16 gather mirrors (ping-pong)
__device__ int    g_deg[Nc];
__device__ float  g_dinv[Nc];
__device__ int    g_rowptr[Nc + 1];
__device__ int    g_cursor[Nc];
__device__ EdgeT  g_csr[Ec];
__device__ float  g_partial[EGRID * Bc * Cc];

// ---------------------------------------------------------------------------
__global__ void k_deg(const int* __restrict__ ei) {
    int e = blockIdx.x * blockDim.x + threadIdx.x;
    if (e < Ec) atomicAdd(&g_deg[ei[e]], 1);   // row = edge_index[0]
}

// dinv + single-block exclusive scan of g_deg -> g_rowptr.
// Re-zeroes g_deg and g_cursor (restores invariant; cursor consumed below).
__global__ void k_scan_dinv() {
    __shared__ int ss[1024];
    const int CH = 20;
    int tid = threadIdx.x;
    int st = tid * CH;
    int s = 0;
    #pragma unroll
    for (int i = 0; i < CH; i++) {
        int idx = st + i;
        if (idx < Nc) {
            int d = g_deg[idx];
            g_dinv[idx] = (d > 0) ? rsqrtf((float)d) : 0.0f;
            s += d;
        }
    }
    ss[tid] = s;
    __syncthreads();
    for (int off = 1; off < 1024; off <<= 1) {
        int v = (tid >= off) ? ss[tid - off] : 0;
        __syncthreads();
        ss[tid] += v;
        __syncthreads();
    }
    int run = ss[tid] - s;   // exclusive prefix of this chunk
    for (int i = 0; i < CH; i++) {
        int idx = st + i;
        if (idx < Nc) {
            int d = g_deg[idx];
            g_rowptr[idx] = run;
            run += d;
            g_deg[idx] = 0;
            g_cursor[idx] = 0;
        }
    }
    if (tid == 1023) g_rowptr[Nc] = ss[1023];
}

// Merged: CSR fill (i < Ec) + plane-0 init fp32 + fp16 mirror (buf 0).
__global__ void k_fill_init(const int* __restrict__ ei, const float* __restrict__ x) {
    int i = blockIdx.x * blockDim.x + threadIdx.x;
    if (i < Ec) {
        int r = ei[i];
        int c = ei[Ec + i];
        int pos = g_rowptr[r] + atomicAdd(&g_cursor[r], 1);
        EdgeT t;
        t.c = c;
        t.w = -(g_dinv[r] * g_dinv[c]);   // norm = -(dinv[row]*dinv[col])
        g_csr[pos] = t;
    }
    if (i < Nc * Fp) {
        int n = i >> 7, f = i & 127;
        float v = 0.0f;
        if (f < Bc * Hc) {
            int b = f / Hc, h = f - b * Hc;
            v = x[((size_t)b * Nc + n) * Hc + h];
        }
        g_TxAll[i] = v;
        g_TxH[0][i] = __float2half(v);
    }
}

// Warp-per-node CSR gather SpMM: out = (first ? L*in : 2*L*in - prev)
// Gathers from the fp16 mirror (240 B/edge -> 2 L1 wavefronts); recursion
// state (prev term, output) stays fp32. Writes fp32 plane + fp16 mirror.
__global__ void __launch_bounds__(256) k_prop(int kprev, int kout, int hin, int first) {
    int warp = blockIdx.x * (blockDim.x >> 5) + (threadIdx.x >> 5);
    int lane = threadIdx.x & 31;
    if (warp >= Nc || lane >= 30) return;   // 30 lanes * 4 feat = 120 features
    const uint2* __restrict__ in2 = (const uint2*)g_TxH[hin];       // 4 halves/lane
    float4* out4 = (float4*)(g_TxAll + (size_t)kout * PLANE);
    uint2* outh = (uint2*)g_TxH[hin ^ 1];
    int s = g_rowptr[warp], e = g_rowptr[warp + 1];
    float4 acc[4];
    #pragma unroll
    for (int q = 0; q < 4; q++) acc[q] = make_float4(0.f, 0.f, 0.f, 0.f);
    int j = s;
    for (; j + 8 <= e; j += 8) {
        EdgeT E[8];
        #pragma unroll
        for (int u = 0; u < 8; u++) E[u] = g_csr[j + u];
        uint2 V[8];
        #pragma unroll
        for (int u = 0; u < 8; u++)
            V[u] = __ldg(&in2[(size_t)E[u].c * 32 + lane]);
        #pragma unroll
        for (int u = 0; u < 8; u++) {
            float w = E[u].w; int q = u & 3;
            float2 f01 = __half22float2(*(const __half2*)&V[u].x);
            float2 f23 = __half22float2(*(const __half2*)&V[u].y);
            acc[q].x = fmaf(w, f01.x, acc[q].x);
            acc[q].y = fmaf(w, f01.y, acc[q].y);
            acc[q].z = fmaf(w, f23.x, acc[q].z);
            acc[q].w = fmaf(w, f23.y, acc[q].w);
        }
    }
    for (; j + 4 <= e; j += 4) {
        EdgeT E[4];
        #pragma unroll
        for (int u = 0; u < 4; u++) E[u] = g_csr[j + u];
        uint2 V[4];
        #pragma unroll
        for (int u = 0; u < 4; u++)
            V[u] = __ldg(&in2[(size_t)E[u].c * 32 + lane]);
        #pragma unroll
        for (int u = 0; u < 4; u++) {
            float w = E[u].w;
            float2 f01 = __half22float2(*(const __half2*)&V[u].x);
            float2 f23 = __half22float2(*(const __half2*)&V[u].y);
            acc[u].x = fmaf(w, f01.x, acc[u].x);
            acc[u].y = fmaf(w, f01.y, acc[u].y);
            acc[u].z = fmaf(w, f23.x, acc[u].z);
            acc[u].w = fmaf(w, f23.y, acc[u].w);
        }
    }
    for (; j < e; j++) {
        EdgeT E0 = g_csr[j];
        uint2 V0 = __ldg(&in2[(size_t)E0.c * 32 + lane]);
        float2 f01 = __half22float2(*(const __half2*)&V0.x);
        float2 f23 = __half22float2(*(const __half2*)&V0.y);
        acc[0].x = fmaf(E0.w, f01.x, acc[0].x);
        acc[0].y = fmaf(E0.w, f01.y, acc[0].y);
        acc[0].z = fmaf(E0.w, f23.x, acc[0].z);
        acc[0].w = fmaf(E0.w, f23.y, acc[0].w);
    }
    float4 a;
    a.x = (acc[0].x + acc[1].x) + (acc[2].x + acc[3].x);
    a.y = (acc[0].y + acc[1].y) + (acc[2].y + acc[3].y);
    a.z = (acc[0].z + acc[1].z) + (acc[2].z + acc[3].z);
    a.w = (acc[0].w + acc[1].w) + (acc[2].w + acc[3].w);
    float4 r;
    if (first) {
        r = a;
    } else {
        const float4* pv = (const float4*)(g_TxAll + (size_t)kprev * PLANE);
        float4 p = pv[(size_t)warp * 32 + lane];
        r.x = fmaf(2.f, a.x, -p.x); r.y = fmaf(2.f, a.y, -p.y);
        r.z = fmaf(2.f, a.z, -p.z); r.w = fmaf(2.f, a.w, -p.w);
    }
    out4[(size_t)warp * 32 + lane] = r;
    uint2 hv;
    *(__half2*)&hv.x = __float22half2_rn(make_float2(r.x, r.y));
    *(__half2*)&hv.y = __float22half2_rn(make_float2(r.z, r.w));
    outh[(size_t)warp * 32 + lane] = hv;
}

// Fused: h[n,b,g] = relu(sum_k Tx_k[n,b,:] @ W[k] + bias); per-block logit
// partials in registers. warp = b, lane handles g = {2l, 2l+1}.
// 4-node register blocking; SMEM rows unpadded (stride 120 floats, 48.0 KB).
__global__ void __launch_bounds__(256) k_einsum(const float* __restrict__ W,
                                               const float* __restrict__ bias,
                                               const float* __restrict__ fc_w) {
    __shared__ float txsh[4 * Kc * Fs];   // 48.0 KB
    int tid = threadIdx.x;
    int b = tid >> 5, lane = tid & 31;
    float p[Cc];
    #pragma unroll
    for (int c = 0; c < Cc; c++) p[c] = 0.f;
    float bi0 = __ldg(&bias[2 * lane]);
    float bi1 = __ldg(&bias[2 * lane + 1]);
    const float4* planes = (const float4*)g_TxAll;

    for (int n0 = blockIdx.x * 4; n0 < Nc; n0 += gridDim.x * 4) {
        float4* t4 = (float4*)txsh;
        for (int i = tid; i < Kc * 4 * 30; i += 256) {
            int k = i / 120;
            int rem = i - k * 120;
            int node = rem / 30, qq = rem - node * 30;
            t4[i] = planes[(size_t)k * (PLANE / 4) + (size_t)(n0 + node) * 32 + qq];
        }
        __syncthreads();
        float a[4][2];
        #pragma unroll
        for (int u = 0; u < 4; u++) { a[u][0] = 0.f; a[u][1] = 0.f; }
        for (int k = 0; k < Kc; k++) {
            const float* tb = txsh + k * (4 * Fs) + b * Hc;
            const float2* wr = (const float2*)(W + (size_t)k * Hc * Gc);
            #pragma unroll
            for (int h = 0; h < Hc; h++) {
                float t0 = tb[h];
                float t1 = tb[Fs + h];
                float t2 = tb[2 * Fs + h];
                float t3 = tb[3 * Fs + h];
                float2 wv = __ldg(&wr[h * 32 + lane]);  // L1-resident
                a[0][0] = fmaf(t0, wv.x, a[0][0]); a[0][1] = fmaf(t0, wv.y, a[0][1]);
                a[1][0] = fmaf(t1, wv.x, a[1][0]); a[1][1] = fmaf(t1, wv.y, a[1][1]);
                a[2][0] = fmaf(t2, wv.x, a[2][0]); a[2][1] = fmaf(t2, wv.y, a[2][1]);
                a[3][0] = fmaf(t3, wv.x, a[3][0]); a[3][1] = fmaf(t3, wv.y, a[3][1]);
            }
        }
        float hh[4][2];
        #pragma unroll
        for (int u = 0; u < 4; u++) {
            hh[u][0] = fmaxf(a[u][0] + bi0, 0.f);
            hh[u][1] = fmaxf(a[u][1] + bi1, 0.f);
        }
        const float* fw = fc_w + (size_t)n0 * Gc + 2 * lane;
        #pragma unroll
        for (int c = 0; c < Cc; c++) {
            const float* fwc = fw + (size_t)c * Nc * Gc;
            #pragma unroll
            for (int u = 0; u < 4; u++) {
                float2 wv = __ldg((const float2*)(fwc + u * Gc));
                p[c] = fmaf(hh[u][0], wv.x, fmaf(hh[u][1], wv.y, p[c]));
            }
        }
        __syncthreads();
    }
    #pragma unroll
    for (int c = 0; c < Cc; c++) {
        #pragma unroll
        for (int off = 16; off > 0; off >>= 1)
            p[c] += __shfl_down_sync(0xffffffffu, p[c], off);
    }
    if (lane == 0) {
        #pragma unroll
        for (int c = 0; c < Cc; c++)
            g_partial[((size_t)blockIdx.x * Bc + b) * Cc + c] = p[c];
    }
}

// Deterministic reduction of partials + fc_b + log_softmax -> d_out [8,6]
__global__ void k_final(const float* __restrict__ fc_b, float* __restrict__ out) {
    __shared__ float lg[Bc * Cc];
    int tid = threadIdx.x;
    if (tid < Bc * Cc) {
        float s = 0.f;
        for (int j = 0; j < EGRID; j++) s += g_partial[j * (Bc * Cc) + tid];
        lg[tid] = s + fc_b[tid % Cc];
    }
    __syncthreads();
    if (tid < Bc) {
        float m = -1e30f;
        #pragma unroll
        for (int c = 0; c < Cc; c++) m = fmaxf(m, lg[tid * Cc + c]);
        float se = 0.f;
        #pragma unroll
        for (int c = 0; c < Cc; c++) se += expf(lg[tid * Cc + c] - m);
        float lse = m + logf(se);
        #pragma unroll
        for (int c = 0; c < Cc; c++) out[tid * Cc + c] = lg[tid * Cc + c] - lse;
    }
}

// ---------------------------------------------------------------------------
extern "C" void kernel_launch(void* const* d_in, const int* in_sizes, int n_in,
                              void* d_out, int out_size) {
    const float* x    = (const float*)d_in[0];   // [B,N,H]
    const int*   ei   = (const int*)d_in[1];     // [2,E]
    const float* W    = (const float*)d_in[2];   // [K,H,G]
    const float* bias = (const float*)d_in[3];   // [G]
    const float* fc_w = (const float*)d_in[4];   // [C, N*G]
    const float* fc_b = (const float*)d_in[5];   // [C]
    float* out = (float*)d_out;                  // [B,C]

    k_deg<<<(Ec + 255) / 256, 256>>>(ei);                       // idx 0
    k_scan_dinv<<<1, 1024>>>();                                 // idx 1
    k_fill_init<<<(Nc * Fp + 255) / 256, 256>>>(ei, x);         // idx 2

    // Chebyshev recursion. Plane k's fp16 mirror lives in buf (k & 1).
    const int PBLK = 256;                 // 8 warps/block, warp-per-node
    const int PGRID = (Nc + 7) / 8;
    // kout=1: gather from mirror of plane0 (buf 0), write buf 1
    k_prop<<<PGRID, PBLK>>>(0, 1, 0, 1);                        // idx 3 <- ncu capture
    for (int k = 2; k < Kc; k++)
        k_prop<<<PGRID, PBLK>>>(k - 2, k, (k - 1) & 1, 0);

    k_einsum<<<EGRID, 256>>>(W, bias, fc_w);
    k_final<<<1, 64>>>(fc_b, out);
}